// round 3
// baseline (speedup 1.0000x reference)
#include <cuda_runtime.h>
#include <cstdint>
#include <cstddef>

#define NN 50000
#define EE 800000
#define HID 128
#define EDIM 32

// ---------------- scratch (static __device__ — allocation-free) ----------------
__device__ __align__(16) float g_x0[(size_t)NN * HID];
__device__ __align__(16) float g_x1[(size_t)NN * HID];
__device__ __align__(16) float g_mx[(size_t)NN * HID];
__device__ __align__(16) float g_me[(size_t)NN * HID];
__device__ __align__(16) float g_scores[NN];
__device__ int g_src[EE];
__device__ int g_dst[EE];
__device__ unsigned g_maxbits;
__device__ float g_sum;

// ---------------- helpers ----------------
__device__ __forceinline__ void red_add_v4(float* addr, float4 v) {
    asm volatile("red.global.add.v4.f32 [%0], {%1,%2,%3,%4};"
                 :: "l"(addr), "f"(v.x), "f"(v.y), "f"(v.z), "f"(v.w)
                 : "memory");
}

__device__ __forceinline__ void fma4(float4& a, float s, const float4& w) {
    a.x += s * w.x; a.y += s * w.y; a.z += s * w.z; a.w += s * w.w;
}

__device__ __forceinline__ unsigned enc_ordered(float f) {
    unsigned b = __float_as_uint(f);
    return (b & 0x80000000u) ? ~b : (b | 0x80000000u);
}
__device__ __forceinline__ float dec_ordered(unsigned u) {
    unsigned b = (u & 0x80000000u) ? (u ^ 0x80000000u) : ~u;
    return __uint_as_float(b);
}

// ---------------- edge index normalization (handles int64 OR int32 input) ----------------
__global__ void convert_edges(const void* __restrict__ ei) {
    __shared__ int is64;
    if (threadIdx.x == 0) {
        // int64 little-endian values < 2^31 => every odd 32-bit word is 0.
        const int* p = (const int*)ei;
        int z = 0;
        #pragma unroll
        for (int i = 0; i < 64; i++) z |= p[2 * i + 1];
        is64 = (z == 0);
    }
    __syncthreads();
    const int idx = blockIdx.x * blockDim.x + threadIdx.x;
    const int stride = gridDim.x * blockDim.x;
    if (is64) {
        const long long* p = (const long long*)ei;
        for (int e = idx; e < EE; e += stride) {
            g_src[e] = (int)p[e];
            g_dst[e] = (int)p[EE + e];
        }
    } else {
        const int* p = (const int*)ei;
        for (int e = idx; e < EE; e += stride) {
            g_src[e] = p[e];
            g_dst[e] = p[EE + e];
        }
    }
}

// ---------------- zero kernels ----------------
__global__ void zero_main() {
    const int n4 = NN * HID / 4;
    float4* a = (float4*)g_me;
    float4* b = (float4*)g_mx;
    const float4 z = make_float4(0.f, 0.f, 0.f, 0.f);
    for (int i = blockIdx.x * blockDim.x + threadIdx.x; i < n4;
         i += gridDim.x * blockDim.x) {
        a[i] = z;
        b[i] = z;
    }
    if (blockIdx.x == 0 && threadIdx.x == 0) { g_maxbits = 0u; g_sum = 0.f; }
}

__global__ void zero_mx() {
    const int n4 = NN * HID / 4;
    float4* b = (float4*)g_mx;
    const float4 z = make_float4(0.f, 0.f, 0.f, 0.f);
    for (int i = blockIdx.x * blockDim.x + threadIdx.x; i < n4;
         i += gridDim.x * blockDim.x)
        b[i] = z;
}

// ---------------- generic row-projection GEMM: out = relu(in @ W + b) ----------------
// Block = 256 threads = 8 warps. Tile = 64 rows x 128 cols.
// Warp w owns rows [w*8, w*8+8), lane owns cols [lane*4, lane*4+4).
// W (K x 128) staged fully in SMEM; input rows staged in SMEM.
template <int K, bool CONCAT>
__global__ void proj_kernel(const float* __restrict__ in0,
                            const float* __restrict__ in1,
                            const float* __restrict__ W,
                            const float* __restrict__ bias,
                            float* __restrict__ out, int rows) {
    extern __shared__ float sh[];
    float* W_s = sh;             // K*128 floats
    float* X_s = sh + K * 128;   // 64*K floats
    const int tid = threadIdx.x;

    {   // stage W (coalesced float4)
        const float4* Wg = (const float4*)W;
        float4* Ws4 = (float4*)W_s;
        const int n4 = K * 128 / 4;
        for (int i = tid; i < n4; i += 256) Ws4[i] = Wg[i];
    }
    const int tile0 = blockIdx.x * 64;
    {   // stage 64 input rows
        float4* Xs4 = (float4*)X_s;
        const int KC = K / 4;
        for (int i = tid; i < 64 * KC; i += 256) {
            const int r = i / KC, kc = i % KC;
            const int g = tile0 + r;
            float4 v = make_float4(0.f, 0.f, 0.f, 0.f);
            if (g < rows) {
                if (CONCAT) {
                    v = (kc < 32) ? ((const float4*)(in0 + (size_t)g * 128))[kc]
                                  : ((const float4*)(in1 + (size_t)g * 128))[kc - 32];
                } else {
                    v = ((const float4*)(in0 + (size_t)g * K))[kc];
                }
            }
            Xs4[i] = v;
        }
    }
    __syncthreads();

    const int lane = tid & 31;
    const int w = tid >> 5;
    const float4 bias4 = ((const float4*)bias)[lane];
    float4 acc[8];
    #pragma unroll
    for (int r = 0; r < 8; r++) acc[r] = bias4;

    const float* Xrow = &X_s[(w * 8) * K];
    for (int k = 0; k < K; k += 4) {
        const float4 w0 = ((const float4*)&W_s[(k + 0) * 128])[lane];
        const float4 w1 = ((const float4*)&W_s[(k + 1) * 128])[lane];
        const float4 w2 = ((const float4*)&W_s[(k + 2) * 128])[lane];
        const float4 w3 = ((const float4*)&W_s[(k + 3) * 128])[lane];
        #pragma unroll
        for (int r = 0; r < 8; r++) {
            const float4 xv = *(const float4*)&Xrow[r * K + k];
            fma4(acc[r], xv.x, w0);
            fma4(acc[r], xv.y, w1);
            fma4(acc[r], xv.z, w2);
            fma4(acc[r], xv.w, w3);
        }
    }

    #pragma unroll
    for (int r = 0; r < 8; r++) {
        const int g = tile0 + w * 8 + r;
        if (g < rows) {
            float4 v;
            v.x = fmaxf(acc[r].x, 0.f);
            v.y = fmaxf(acc[r].y, 0.f);
            v.z = fmaxf(acc[r].z, 0.f);
            v.w = fmaxf(acc[r].w, 0.f);
            ((float4*)(out + (size_t)g * 128))[lane] = v;
        }
    }
}

// ---------------- fused edge projection + segment-sum into m_e ----------------
// m_e[dst[e]] += relu(EF[e] @ We + be), never materializing edge_attr.
__global__ void edge_proj_kernel(const float* __restrict__ EF,
                                 const float* __restrict__ W,
                                 const float* __restrict__ bias) {
    __shared__ __align__(16) float W_s[EDIM * 128];   // 16 KB
    __shared__ __align__(16) float X_s[64 * EDIM];    // 8 KB
    __shared__ int dst_s[64];
    const int tid = threadIdx.x;

    for (int i = tid; i < EDIM * 128 / 4; i += 256)
        ((float4*)W_s)[i] = ((const float4*)W)[i];

    const int tile0 = blockIdx.x * 64;
    {
        const int KC = EDIM / 4;  // 8
        for (int i = tid; i < 64 * KC; i += 256) {
            const int r = i / KC, kc = i % KC;
            const int g = tile0 + r;
            ((float4*)X_s)[i] = (g < EE)
                ? ((const float4*)(EF + (size_t)g * EDIM))[kc]
                : make_float4(0.f, 0.f, 0.f, 0.f);
        }
    }
    if (tid < 64) {
        const int g = tile0 + tid;
        dst_s[tid] = (g < EE) ? g_dst[g] : 0;
    }
    __syncthreads();

    const int lane = tid & 31;
    const int w = tid >> 5;
    const float4 bias4 = ((const float4*)bias)[lane];
    float4 acc[8];
    #pragma unroll
    for (int r = 0; r < 8; r++) acc[r] = bias4;

    const float* Xrow = &X_s[(w * 8) * EDIM];
    #pragma unroll
    for (int k = 0; k < EDIM; k += 4) {
        const float4 w0 = ((const float4*)&W_s[(k + 0) * 128])[lane];
        const float4 w1 = ((const float4*)&W_s[(k + 1) * 128])[lane];
        const float4 w2 = ((const float4*)&W_s[(k + 2) * 128])[lane];
        const float4 w3 = ((const float4*)&W_s[(k + 3) * 128])[lane];
        #pragma unroll
        for (int r = 0; r < 8; r++) {
            const float4 xv = *(const float4*)&Xrow[r * EDIM + k];
            fma4(acc[r], xv.x, w0);
            fma4(acc[r], xv.y, w1);
            fma4(acc[r], xv.z, w2);
            fma4(acc[r], xv.w, w3);
        }
    }

    #pragma unroll
    for (int r = 0; r < 8; r++) {
        const int g = tile0 + w * 8 + r;
        if (g < EE) {
            float4 v;
            v.x = fmaxf(acc[r].x, 0.f);
            v.y = fmaxf(acc[r].y, 0.f);
            v.z = fmaxf(acc[r].z, 0.f);
            v.w = fmaxf(acc[r].w, 0.f);
            red_add_v4(&g_me[(size_t)dst_s[w * 8 + r] * 128 + lane * 4], v);
        }
    }
}

// ---------------- m_x[dst] += x[src] (warp per edge, v4 atomics) ----------------
__global__ void gather_scatter(const float* __restrict__ x) {
    const int lane = threadIdx.x & 31;
    const int warp = (blockIdx.x * blockDim.x + threadIdx.x) >> 5;
    const int nwarps = (gridDim.x * blockDim.x) >> 5;
    for (int e = warp; e < EE; e += nwarps) {
        const int s = g_src[e];
        const int d = g_dst[e];
        const float4 v = ((const float4*)(x + (size_t)s * 128))[lane];
        red_add_v4(&g_mx[(size_t)d * 128 + lane * 4], v);
    }
}

// ---------------- scores + global max ----------------
__global__ void scores_kernel(const float* __restrict__ x,
                              const float* __restrict__ Wo,
                              const float* __restrict__ bo) {
    const int lane = threadIdx.x & 31;
    const int w = threadIdx.x >> 5;
    const int nw = blockDim.x >> 5;
    const float4 wv = ((const float4*)Wo)[lane];
    const float b = *bo;
    float lmax = -3.402823466e38f;
    for (int n = blockIdx.x * nw + w; n < NN; n += gridDim.x * nw) {
        const float4 xv = ((const float4*)(x + (size_t)n * 128))[lane];
        float d = xv.x * wv.x + xv.y * wv.y + xv.z * wv.z + xv.w * wv.w;
        #pragma unroll
        for (int o = 16; o; o >>= 1) d += __shfl_down_sync(0xffffffffu, d, o);
        if (lane == 0) {
            const float sc = d + b;
            g_scores[n] = sc;
            if (sc > lmax) lmax = sc;
        }
    }
    __shared__ float sm[8];
    lmax = __shfl_sync(0xffffffffu, lmax, 0);
    if (lane == 0) sm[w] = lmax;
    __syncthreads();
    if (threadIdx.x == 0) {
        float m = sm[0];
        for (int i = 1; i < nw; i++) m = fmaxf(m, sm[i]);
        atomicMax(&g_maxbits, enc_ordered(m));
    }
}

// ---------------- sum of exp ----------------
__global__ void sum_kernel() {
    const float maxf = dec_ordered(g_maxbits);
    float s = 0.f;
    for (int n = blockIdx.x * blockDim.x + threadIdx.x; n < NN;
         n += gridDim.x * blockDim.x)
        s += expf(g_scores[n] - maxf);
    #pragma unroll
    for (int o = 16; o; o >>= 1) s += __shfl_down_sync(0xffffffffu, s, o);
    __shared__ float sm[8];
    const int lane = threadIdx.x & 31, w = threadIdx.x >> 5;
    if (lane == 0) sm[w] = s;
    __syncthreads();
    if (threadIdx.x == 0) {
        float t = 0.f;
        const int nw = blockDim.x >> 5;
        for (int i = 0; i < nw; i++) t += sm[i];
        atomicAdd(&g_sum, t);
    }
}

// ---------------- normalize ----------------
__global__ void finalize_kernel(float* __restrict__ out) {
    const float maxf = dec_ordered(g_maxbits);
    const float inv = 1.0f / g_sum;
    const int n = blockIdx.x * blockDim.x + threadIdx.x;
    if (n < NN) out[n] = expf(g_scores[n] - maxf) * inv;
}

// ---------------- launch ----------------
extern "C" void kernel_launch(void* const* d_in, const int* in_sizes, int n_in,
                              void* d_out, int out_size) {
    const float* NF = (const float*)d_in[0];
    const float* EF = (const float*)d_in[1];
    const float* Wn = (const float*)d_in[2];
    const float* bn = (const float*)d_in[3];
    const float* We = (const float*)d_in[4];
    const float* be = (const float*)d_in[5];
    const float* W1 = (const float*)d_in[6];
    const float* b1 = (const float*)d_in[7];
    const float* W2 = (const float*)d_in[8];
    const float* b2 = (const float*)d_in[9];
    const float* Wo = (const float*)d_in[10];
    const float* bo = (const float*)d_in[11];
    const void*  EI = d_in[12];
    float* out = (float*)d_out;

    float *px0, *px1, *pmx, *pme;
    cudaGetSymbolAddress((void**)&px0, g_x0);
    cudaGetSymbolAddress((void**)&px1, g_x1);
    cudaGetSymbolAddress((void**)&pmx, g_mx);
    cudaGetSymbolAddress((void**)&pme, g_me);

    const int SMEM_128 = (128 * 128 + 64 * 128) * 4;   // 96 KB
    const int SMEM_256 = (256 * 128 + 64 * 256) * 4;   // 192 KB
    cudaFuncSetAttribute(proj_kernel<128, false>,
                         cudaFuncAttributeMaxDynamicSharedMemorySize, SMEM_128);
    cudaFuncSetAttribute(proj_kernel<256, true>,
                         cudaFuncAttributeMaxDynamicSharedMemorySize, SMEM_256);

    const int nTilesN = (NN + 63) / 64;   // 782
    const int nTilesE = EE / 64;          // 12500

    // normalize edge indices (int64/int32 agnostic)
    convert_edges<<<512, 256>>>(EI);
    // zero m_e, m_x, scalars
    zero_main<<<2048, 256>>>();
    // x0 = relu(NF @ Wn + bn)
    proj_kernel<128, false><<<nTilesN, 256, SMEM_128>>>(NF, nullptr, Wn, bn, px0, NN);
    // m_e = segment_sum(relu(EF @ We + be), dst)   [computed once, reused by both layers]
    edge_proj_kernel<<<nTilesE, 256>>>(EF, We, be);
    // layer 1
    gather_scatter<<<1184, 256>>>(px0);
    proj_kernel<256, true><<<nTilesN, 256, SMEM_256>>>(pmx, pme, W1, b1, px1, NN);
    // layer 2
    zero_mx<<<2048, 256>>>();
    gather_scatter<<<1184, 256>>>(px1);
    proj_kernel<256, true><<<nTilesN, 256, SMEM_256>>>(pmx, pme, W2, b2, px0, NN);
    // scores + softmax
    scores_kernel<<<512, 128>>>(px0, Wo, bo);
    sum_kernel<<<512, 256>>>();
    finalize_kernel<<<(NN + 255) / 256, 256>>>(out);
}

// round 4
// speedup vs baseline: 1.0927x; 1.0927x over previous
#include <cuda_runtime.h>
#include <cstdint>
#include <cstddef>

#define NN 50000
#define EE 800000
#define HID 128
#define EDIM 32
#define XSTR 66   // padded row-transposed X stride (even -> 8B aligned LDS.64)

// ---------------- scratch (static __device__ — allocation-free) ----------------
__device__ __align__(16) float g_x0[(size_t)NN * HID];
__device__ __align__(16) float g_x1[(size_t)NN * HID];
__device__ __align__(16) float g_mx[(size_t)NN * HID];
__device__ __align__(16) float g_me[(size_t)NN * HID];
__device__ __align__(16) float g_scores[NN];
__device__ int g_src[EE];
__device__ int g_dst[EE];
__device__ unsigned g_maxbits;
__device__ float g_sum;

// ---------------- helpers ----------------
__device__ __forceinline__ void red_add_v4(float* addr, float4 v) {
    asm volatile("red.global.add.v4.f32 [%0], {%1,%2,%3,%4};"
                 :: "l"(addr), "f"(v.x), "f"(v.y), "f"(v.z), "f"(v.w)
                 : "memory");
}

// packed f32x2 FMA: d = a*b + c (two fp32 lanes per instruction)
__device__ __forceinline__ unsigned long long fma2(unsigned long long a,
                                                   unsigned long long b,
                                                   unsigned long long c) {
    unsigned long long d;
    asm("fma.rn.f32x2 %0, %1, %2, %3;" : "=l"(d) : "l"(a), "l"(b), "l"(c));
    return d;
}
__device__ __forceinline__ unsigned long long dup2(float s) {
    unsigned long long d;
    asm("mov.b64 %0, {%1, %1};" : "=l"(d) : "f"(s));
    return d;
}
__device__ __forceinline__ void unpack2(unsigned long long v, float& lo, float& hi) {
    asm("mov.b64 {%0, %1}, %2;" : "=f"(lo), "=f"(hi) : "l"(v));
}

__device__ __forceinline__ unsigned enc_ordered(float f) {
    unsigned b = __float_as_uint(f);
    return (b & 0x80000000u) ? ~b : (b | 0x80000000u);
}
__device__ __forceinline__ float dec_ordered(unsigned u) {
    unsigned b = (u & 0x80000000u) ? (u ^ 0x80000000u) : ~u;
    return __uint_as_float(b);
}

// ---------------- edge index normalization (int64 OR int32 input) ----------------
__global__ void convert_edges(const void* __restrict__ ei) {
    __shared__ int is64;
    if (threadIdx.x == 0) {
        const int* p = (const int*)ei;
        int z = 0;
        #pragma unroll
        for (int i = 0; i < 64; i++) z |= p[2 * i + 1];
        is64 = (z == 0);
    }
    __syncthreads();
    const int idx = blockIdx.x * blockDim.x + threadIdx.x;
    const int stride = gridDim.x * blockDim.x;
    if (is64) {
        const long long* p = (const long long*)ei;
        for (int e = idx; e < EE; e += stride) {
            g_src[e] = (int)p[e];
            g_dst[e] = (int)p[EE + e];
        }
    } else {
        const int* p = (const int*)ei;
        for (int e = idx; e < EE; e += stride) {
            g_src[e] = p[e];
            g_dst[e] = p[EE + e];
        }
    }
}

// ---------------- zero kernels ----------------
__global__ void zero_main() {
    const int n4 = NN * HID / 4;
    float4* a = (float4*)g_me;
    float4* b = (float4*)g_mx;
    const float4 z = make_float4(0.f, 0.f, 0.f, 0.f);
    for (int i = blockIdx.x * blockDim.x + threadIdx.x; i < n4;
         i += gridDim.x * blockDim.x) {
        a[i] = z;
        b[i] = z;
    }
    if (blockIdx.x == 0 && threadIdx.x == 0) { g_maxbits = 0u; g_sum = 0.f; }
}

__global__ void zero_mx() {
    const int n4 = NN * HID / 4;
    float4* b = (float4*)g_mx;
    const float4 z = make_float4(0.f, 0.f, 0.f, 0.f);
    for (int i = blockIdx.x * blockDim.x + threadIdx.x; i < n4;
         i += gridDim.x * blockDim.x)
        b[i] = z;
}

// ---------------- f32x2 row-projection GEMM: out = relu(in @ W + b) ----------------
// Block = 256 threads = 8 warps. Tile = 64 rows x 128 cols.
// Warp w owns rows [w*8, w*8+8) as 4 row-PAIRS; lane owns cols [lane*4, lane*4+4).
// X staged TRANSPOSED in smem (X_s[k*XSTR + row]) so a row-pair is one LDS.64
// broadcast; W broadcast-scalar is dup'd once and shared by 4 row-pairs.
// Inner loop per k: 16 FMA2 (=32 FMAs) + 4 dup movs + 1 LDS.128 + 4 bcast LDS.64.
template <int K, bool CONCAT>
__global__ void proj_kernel(const float* __restrict__ in0,
                            const float* __restrict__ in1,
                            const float* __restrict__ W,
                            const float* __restrict__ bias,
                            float* __restrict__ out, int rows) {
    extern __shared__ float sh[];
    float* W_s = sh;             // K*128 floats
    float* X_s = sh + K * 128;   // K*XSTR floats (transposed, padded)
    const int tid = threadIdx.x;

    {   // stage W (coalesced float4)
        const float4* Wg = (const float4*)W;
        float4* Ws4 = (float4*)W_s;
        const int n4 = K * 128 / 4;
        for (int i = tid; i < n4; i += 256) Ws4[i] = Wg[i];
    }
    const int tile0 = blockIdx.x * 64;
    {   // stage 64 rows transposed: warp lanes cover consecutive rows -> STS conflict-free
        const int KC = K / 4;
        for (int i = tid; i < 64 * KC; i += 256) {
            const int r = i & 63, kc = i >> 6;
            const int g = tile0 + r;
            float4 v = make_float4(0.f, 0.f, 0.f, 0.f);
            if (g < rows) {
                if (CONCAT) {
                    v = (kc < 32) ? ((const float4*)(in0 + (size_t)g * 128))[kc]
                                  : ((const float4*)(in1 + (size_t)g * 128))[kc - 32];
                } else {
                    v = ((const float4*)(in0 + (size_t)g * K))[kc];
                }
            }
            float* xp = &X_s[(kc * 4) * XSTR + r];
            xp[0 * XSTR] = v.x;
            xp[1 * XSTR] = v.y;
            xp[2 * XSTR] = v.z;
            xp[3 * XSTR] = v.w;
        }
    }
    __syncthreads();

    const int lane = tid & 31;
    const int w = tid >> 5;
    const int rb = w * 8;
    const float4 bias4 = ((const float4*)bias)[lane];
    unsigned long long acc[4][4];
    {
        const unsigned long long b0 = dup2(bias4.x), b1 = dup2(bias4.y);
        const unsigned long long b2 = dup2(bias4.z), b3 = dup2(bias4.w);
        #pragma unroll
        for (int p = 0; p < 4; p++) {
            acc[p][0] = b0; acc[p][1] = b1; acc[p][2] = b2; acc[p][3] = b3;
        }
    }

    #pragma unroll 4
    for (int k = 0; k < K; k++) {
        const float4 wv = ((const float4*)&W_s[k * 128])[lane];
        const unsigned long long w0 = dup2(wv.x), w1 = dup2(wv.y);
        const unsigned long long w2 = dup2(wv.z), w3 = dup2(wv.w);
        const float* xb = &X_s[k * XSTR + rb];
        #pragma unroll
        for (int p = 0; p < 4; p++) {
            const unsigned long long xp = *(const unsigned long long*)(xb + 2 * p);
            acc[p][0] = fma2(xp, w0, acc[p][0]);
            acc[p][1] = fma2(xp, w1, acc[p][1]);
            acc[p][2] = fma2(xp, w2, acc[p][2]);
            acc[p][3] = fma2(xp, w3, acc[p][3]);
        }
    }

    #pragma unroll
    for (int p = 0; p < 4; p++) {
        float4 v0, v1;
        unpack2(acc[p][0], v0.x, v1.x);
        unpack2(acc[p][1], v0.y, v1.y);
        unpack2(acc[p][2], v0.z, v1.z);
        unpack2(acc[p][3], v0.w, v1.w);
        const int g0 = tile0 + rb + 2 * p;
        if (g0 < rows) {
            v0.x = fmaxf(v0.x, 0.f); v0.y = fmaxf(v0.y, 0.f);
            v0.z = fmaxf(v0.z, 0.f); v0.w = fmaxf(v0.w, 0.f);
            ((float4*)(out + (size_t)g0 * 128))[lane] = v0;
        }
        if (g0 + 1 < rows) {
            v1.x = fmaxf(v1.x, 0.f); v1.y = fmaxf(v1.y, 0.f);
            v1.z = fmaxf(v1.z, 0.f); v1.w = fmaxf(v1.w, 0.f);
            ((float4*)(out + (size_t)(g0 + 1) * 128))[lane] = v1;
        }
    }
}

// ---------------- fused edge projection + segment-sum into m_e (f32x2) ----------------
// m_e[dst[e]] += relu(EF[e] @ We + be), edge_attr never materialized.
// EE % 64 == 0, so no bounds checks.
__global__ void edge_proj_kernel(const float* __restrict__ EF,
                                 const float* __restrict__ W,
                                 const float* __restrict__ bias) {
    __shared__ __align__(16) float W_s[EDIM * 128];     // 16 KB
    __shared__ __align__(16) float X_s[EDIM * XSTR];    // 8.25 KB, transposed
    __shared__ int dst_s[64];
    const int tid = threadIdx.x;

    for (int i = tid; i < EDIM * 128 / 4; i += 256)
        ((float4*)W_s)[i] = ((const float4*)W)[i];

    const int tile0 = blockIdx.x * 64;
    {   // transpose-stage 64 edge rows (KC = 8)
        for (int i = tid; i < 64 * (EDIM / 4); i += 256) {
            const int r = i & 63, kc = i >> 6;
            const float4 v = ((const float4*)(EF + (size_t)(tile0 + r) * EDIM))[kc];
            float* xp = &X_s[(kc * 4) * XSTR + r];
            xp[0 * XSTR] = v.x;
            xp[1 * XSTR] = v.y;
            xp[2 * XSTR] = v.z;
            xp[3 * XSTR] = v.w;
        }
    }
    if (tid < 64) dst_s[tid] = g_dst[tile0 + tid];
    __syncthreads();

    const int lane = tid & 31;
    const int w = tid >> 5;
    const int rb = w * 8;
    const float4 bias4 = ((const float4*)bias)[lane];
    unsigned long long acc[4][4];
    {
        const unsigned long long b0 = dup2(bias4.x), b1 = dup2(bias4.y);
        const unsigned long long b2 = dup2(bias4.z), b3 = dup2(bias4.w);
        #pragma unroll
        for (int p = 0; p < 4; p++) {
            acc[p][0] = b0; acc[p][1] = b1; acc[p][2] = b2; acc[p][3] = b3;
        }
    }

    #pragma unroll
    for (int k = 0; k < EDIM; k++) {
        const float4 wv = ((const float4*)&W_s[k * 128])[lane];
        const unsigned long long w0 = dup2(wv.x), w1 = dup2(wv.y);
        const unsigned long long w2 = dup2(wv.z), w3 = dup2(wv.w);
        const float* xb = &X_s[k * XSTR + rb];
        #pragma unroll
        for (int p = 0; p < 4; p++) {
            const unsigned long long xp = *(const unsigned long long*)(xb + 2 * p);
            acc[p][0] = fma2(xp, w0, acc[p][0]);
            acc[p][1] = fma2(xp, w1, acc[p][1]);
            acc[p][2] = fma2(xp, w2, acc[p][2]);
            acc[p][3] = fma2(xp, w3, acc[p][3]);
        }
    }

    #pragma unroll
    for (int p = 0; p < 4; p++) {
        float4 v0, v1;
        unpack2(acc[p][0], v0.x, v1.x);
        unpack2(acc[p][1], v0.y, v1.y);
        unpack2(acc[p][2], v0.z, v1.z);
        unpack2(acc[p][3], v0.w, v1.w);
        v0.x = fmaxf(v0.x, 0.f); v0.y = fmaxf(v0.y, 0.f);
        v0.z = fmaxf(v0.z, 0.f); v0.w = fmaxf(v0.w, 0.f);
        v1.x = fmaxf(v1.x, 0.f); v1.y = fmaxf(v1.y, 0.f);
        v1.z = fmaxf(v1.z, 0.f); v1.w = fmaxf(v1.w, 0.f);
        const int r0 = rb + 2 * p;
        red_add_v4(&g_me[(size_t)dst_s[r0] * 128 + lane * 4], v0);
        red_add_v4(&g_me[(size_t)dst_s[r0 + 1] * 128 + lane * 4], v1);
    }
}

// ---------------- m_x[dst] += x[src] (warp per edge, v4 atomics) ----------------
__global__ void gather_scatter(const float* __restrict__ x) {
    const int lane = threadIdx.x & 31;
    const int warp = (blockIdx.x * blockDim.x + threadIdx.x) >> 5;
    const int nwarps = (gridDim.x * blockDim.x) >> 5;
    for (int e = warp; e < EE; e += nwarps) {
        const int s = g_src[e];
        const int d = g_dst[e];
        const float4 v = ((const float4*)(x + (size_t)s * 128))[lane];
        red_add_v4(&g_mx[(size_t)d * 128 + lane * 4], v);
    }
}

// ---------------- scores + global max ----------------
__global__ void scores_kernel(const float* __restrict__ x,
                              const float* __restrict__ Wo,
                              const float* __restrict__ bo) {
    const int lane = threadIdx.x & 31;
    const int w = threadIdx.x >> 5;
    const int nw = blockDim.x >> 5;
    const float4 wv = ((const float4*)Wo)[lane];
    const float b = *bo;
    float lmax = -3.402823466e38f;
    for (int n = blockIdx.x * nw + w; n < NN; n += gridDim.x * nw) {
        const float4 xv = ((const float4*)(x + (size_t)n * 128))[lane];
        float d = xv.x * wv.x + xv.y * wv.y + xv.z * wv.z + xv.w * wv.w;
        #pragma unroll
        for (int o = 16; o; o >>= 1) d += __shfl_down_sync(0xffffffffu, d, o);
        if (lane == 0) {
            const float sc = d + b;
            g_scores[n] = sc;
            if (sc > lmax) lmax = sc;
        }
    }
    __shared__ float sm[8];
    lmax = __shfl_sync(0xffffffffu, lmax, 0);
    if (lane == 0) sm[w] = lmax;
    __syncthreads();
    if (threadIdx.x == 0) {
        float m = sm[0];
        for (int i = 1; i < nw; i++) m = fmaxf(m, sm[i]);
        atomicMax(&g_maxbits, enc_ordered(m));
    }
}

// ---------------- sum of exp ----------------
__global__ void sum_kernel() {
    const float maxf = dec_ordered(g_maxbits);
    float s = 0.f;
    for (int n = blockIdx.x * blockDim.x + threadIdx.x; n < NN;
         n += gridDim.x * blockDim.x)
        s += expf(g_scores[n] - maxf);
    #pragma unroll
    for (int o = 16; o; o >>= 1) s += __shfl_down_sync(0xffffffffu, s, o);
    __shared__ float sm[8];
    const int lane = threadIdx.x & 31, w = threadIdx.x >> 5;
    if (lane == 0) sm[w] = s;
    __syncthreads();
    if (threadIdx.x == 0) {
        float t = 0.f;
        const int nw = blockDim.x >> 5;
        for (int i = 0; i < nw; i++) t += sm[i];
        atomicAdd(&g_sum, t);
    }
}

// ---------------- normalize ----------------
__global__ void finalize_kernel(float* __restrict__ out) {
    const float maxf = dec_ordered(g_maxbits);
    const float inv = 1.0f / g_sum;
    const int n = blockIdx.x * blockDim.x + threadIdx.x;
    if (n < NN) out[n] = expf(g_scores[n] - maxf) * inv;
}

// ---------------- launch ----------------
extern "C" void kernel_launch(void* const* d_in, const int* in_sizes, int n_in,
                              void* d_out, int out_size) {
    const float* NF = (const float*)d_in[0];
    const float* EF = (const float*)d_in[1];
    const float* Wn = (const float*)d_in[2];
    const float* bn = (const float*)d_in[3];
    const float* We = (const float*)d_in[4];
    const float* be = (const float*)d_in[5];
    const float* W1 = (const float*)d_in[6];
    const float* b1 = (const float*)d_in[7];
    const float* W2 = (const float*)d_in[8];
    const float* b2 = (const float*)d_in[9];
    const float* Wo = (const float*)d_in[10];
    const float* bo = (const float*)d_in[11];
    const void*  EI = d_in[12];
    float* out = (float*)d_out;

    float *px0, *px1, *pmx, *pme;
    cudaGetSymbolAddress((void**)&px0, g_x0);
    cudaGetSymbolAddress((void**)&px1, g_x1);
    cudaGetSymbolAddress((void**)&pmx, g_mx);
    cudaGetSymbolAddress((void**)&pme, g_me);

    const int SMEM_128 = (128 * 128 + 128 * XSTR) * 4;   // ~97 KB
    const int SMEM_256 = (256 * 128 + 256 * XSTR) * 4;   // ~194 KB
    cudaFuncSetAttribute(proj_kernel<128, false>,
                         cudaFuncAttributeMaxDynamicSharedMemorySize, SMEM_128);
    cudaFuncSetAttribute(proj_kernel<256, true>,
                         cudaFuncAttributeMaxDynamicSharedMemorySize, SMEM_256);

    const int nTilesN = (NN + 63) / 64;   // 782
    const int nTilesE = EE / 64;          // 12500

    // normalize edge indices (int64/int32 agnostic)
    convert_edges<<<512, 256>>>(EI);
    // zero m_e, m_x, scalars
    zero_main<<<2048, 256>>>();
    // x0 = relu(NF @ Wn + bn)
    proj_kernel<128, false><<<nTilesN, 256, SMEM_128>>>(NF, nullptr, Wn, bn, px0, NN);
    // m_e = segment_sum(relu(EF @ We + be), dst)   [computed once, reused by both layers]
    edge_proj_kernel<<<nTilesE, 256>>>(EF, We, be);
    // layer 1
    gather_scatter<<<1184, 256>>>(px0);
    proj_kernel<256, true><<<nTilesN, 256, SMEM_256>>>(pmx, pme, W1, b1, px1, NN);
    // layer 2
    zero_mx<<<2048, 256>>>();
    gather_scatter<<<1184, 256>>>(px1);
    proj_kernel<256, true><<<nTilesN, 256, SMEM_256>>>(pmx, pme, W2, b2, px0, NN);
    // scores + softmax
    scores_kernel<<<512, 128>>>(px0, Wo, bo);
    sum_kernel<<<512, 256>>>();
    finalize_kernel<<<(NN + 255) / 256, 256>>>(out);
}